// round 12
// baseline (speedup 1.0000x reference)
#include <cuda_runtime.h>
#include <cuda_fp16.h>
#include <stdint.h>

#define TPB 256

// ---- dynamic smem layout (byte offsets) ----
// planes: 256 rows x 128 B, SW128-swizzled (chunk ^= row&7)
#define OFF_P0     0         // 32768
#define OFF_P1     32768     // 32768
#define OFF_D      65536     // 1024 fp32
#define OFF_Z      69632     // 32 fp32
#define OFF_SMOOTH 69760     // 256 fp32
#define OFF_BIAS   70784     // 704 fp32: b0|b1|b2|b3|b4|b5|b6
#define OFF_AEV    73600     // 8 warps * 256 fp32
#define OFF_W0     81792     // 576 fp32
#define SMEM_BYTES 84096

// swizzled byte offset within a plane: row, 16B-chunk (0..7), byte-in-chunk added by caller
__device__ __forceinline__ int swz(int row, int chunk) {
    return row * 128 + (((chunk) ^ (row & 7)) << 4);
}

// weight fragments packed as PAIRS of adjacent n-tiles -> one uint4 (LDG.128)
__device__ uint4 g_w14frag[2048];   // W1..W4: 512 uint4 per layer
__device__ uint4 g_w5frag[1024];    // W5
__device__ uint4 g_w6frag[4096];    // W6
__device__ float g_part[2048 * 256];

__device__ __forceinline__ uint32_t cvta_sh(const void* p) {
    return (uint32_t)__cvta_generic_to_shared(p);
}
__device__ __forceinline__ void ldsm4(uint32_t* r, uint32_t addr) {
    asm volatile("ldmatrix.sync.aligned.m8n8.x4.shared.b16 {%0,%1,%2,%3}, [%4];"
        : "=r"(r[0]), "=r"(r[1]), "=r"(r[2]), "=r"(r[3]) : "r"(addr));
}
__device__ __forceinline__ void mma16816(float* d, const uint32_t* a, uint32_t b0, uint32_t b1) {
    asm volatile("mma.sync.aligned.m16n8k16.row.col.f32.f16.f16.f32 "
        "{%0,%1,%2,%3}, {%4,%5,%6,%7}, {%8,%9}, {%0,%1,%2,%3};"
        : "+f"(d[0]), "+f"(d[1]), "+f"(d[2]), "+f"(d[3])
        : "r"(a[0]), "r"(a[1]), "r"(a[2]), "r"(a[3]), "r"(b0), "r"(b1));
}
__device__ __forceinline__ uint32_t tanh2(float a, float b) {
    __half2 h = __floats2half2_rn(a, b);
    uint32_t u = *reinterpret_cast<uint32_t*>(&h);
    uint32_t y;
    asm("tanh.approx.f16x2 %0, %1;" : "=r"(y) : "r"(u));
    return y;
}
__device__ __forceinline__ uint32_t hadd2u(uint32_t a, uint32_t b) {
    uint32_t y;
    asm("add.f16x2 %0, %1, %2;" : "=r"(y) : "r"(a), "r"(b));
    return y;
}
__device__ __forceinline__ float tanh_hw(float x) {
    float y;
    asm("tanh.approx.f32 %0, %1;" : "=f"(y) : "f"(x));
    return y;
}
__device__ __forceinline__ float fC_cut(float d) {
    return 0.5f * cosf(0.89759790102565521f * d) + 0.5f;
}

// pack weights into PAIRED B fragments. 7168 threads.
__global__ void pack_weights(const float* __restrict__ W1, const float* __restrict__ W2,
                             const float* __restrict__ W3, const float* __restrict__ W4,
                             const float* __restrict__ W5, const float* __restrict__ W6) {
    int t = blockIdx.x * 256 + threadIdx.x;
    if (t >= 7168) return;
    int gi = t >> 5, l = t & 31;
    const float* W; uint4* dst; int nch, p, ks, N, idx;
    if (gi < 64) {
        int L = gi >> 4, rel = gi & 15;
        W = (L == 0) ? W1 : (L == 1) ? W2 : (L == 2) ? W3 : W4;
        nch = rel >> 3; p = (rel >> 2) & 1; ks = rel & 3;
        dst = g_w14frag + L * 512; N = 64;
        idx = ((nch * 2 + p) * 4 + ks) * 32 + l;
    } else if (gi < 96) {
        int rel = gi - 64;
        W = W5; nch = rel >> 3; p = (rel >> 2) & 1; ks = rel & 3;
        dst = g_w5frag; N = 128;
        idx = ((nch * 2 + p) * 4 + ks) * 32 + l;
    } else {
        int rel = gi - 96;
        W = W6; nch = rel >> 4; p = (rel >> 3) & 1; ks = rel & 7;
        dst = g_w6frag; N = 256;
        idx = ((nch * 2 + p) * 8 + ks) * 32 + l;
    }
    int k = ks * 16 + (l & 3) * 2;
    int r = l >> 2;
    uint4 u;
    {
        int n = (nch * 4 + 2 * p) * 8 + r;
        __half2 h0 = __floats2half2_rn(W[k * N + n], W[(k + 1) * N + n]);
        __half2 h1 = __floats2half2_rn(W[(k + 8) * N + n], W[(k + 9) * N + n]);
        u.x = *reinterpret_cast<uint32_t*>(&h0);
        u.y = *reinterpret_cast<uint32_t*>(&h1);
    }
    {
        int n = (nch * 4 + 2 * p + 1) * 8 + r;
        __half2 h0 = __floats2half2_rn(W[k * N + n], W[(k + 1) * N + n]);
        __half2 h1 = __floats2half2_rn(W[(k + 8) * N + n], W[(k + 9) * N + n]);
        u.z = *reinterpret_cast<uint32_t*>(&h0);
        u.w = *reinterpret_cast<uint32_t*>(&h1);
    }
    dst[idx] = u;
}

__global__ void reduce_out(float* __restrict__ out) {
    int i = blockIdx.x * 512 + threadIdx.x;
    int center = i >> 8, c = i & 255;
    out[i] = g_part[center * 512 + c] + g_part[center * 512 + 256 + c];
}

// 64->64 mma layer, warp owns 32 rows. Swizzled planes; nch fully unrolled.
template<int MODE>
__device__ __forceinline__ void layerG(char* sm8, int srcOff, int dstOff, int resOff,
                                       const uint4* __restrict__ frag,
                                       const float* bias, int lane, int R0)
{
    const int gid = lane >> 2, tig = lane & 3;
    const int arow = R0 + (lane & 15);      // ldsm source row
    const int h = lane >> 4;                // 16B half selector
    const int ax7 = lane & 7;               // arow & 7
    uint32_t aRowBase = cvta_sh(sm8 + srcOff) + arow * 128;
    uint32_t parked[16];
    __syncwarp();
    uint32_t a[4][2][4];
    #pragma unroll
    for (int ks = 0; ks < 4; ks++)
        #pragma unroll
        for (int m = 0; m < 2; m++)
            ldsm4(a[ks][m], aRowBase + m * 2048 + ((((2 * ks) | h) ^ ax7) << 4));
    #pragma unroll
    for (int nch = 0; nch < 2; nch++) {
        float acc[2][4][4];
        #pragma unroll
        for (int nt = 0; nt < 4; nt++) {
            float2 bc = *reinterpret_cast<const float2*>(bias + nch * 32 + nt * 8 + tig * 2);
            #pragma unroll
            for (int m = 0; m < 2; m++) {
                acc[m][nt][0] = bc.x; acc[m][nt][1] = bc.y;
                acc[m][nt][2] = bc.x; acc[m][nt][3] = bc.y;
            }
        }
        #pragma unroll
        for (int ks = 0; ks < 4; ks++) {
            uint4 bw0 = __ldg(frag + ((nch * 2 + 0) * 4 + ks) * 32 + lane);
            uint4 bw1 = __ldg(frag + ((nch * 2 + 1) * 4 + ks) * 32 + lane);
            #pragma unroll
            for (int m = 0; m < 2; m++) {
                mma16816(acc[m][0], a[ks][m], bw0.x, bw0.y);
                mma16816(acc[m][1], a[ks][m], bw0.z, bw0.w);
                mma16816(acc[m][2], a[ks][m], bw1.x, bw1.y);
                mma16816(acc[m][3], a[ks][m], bw1.z, bw1.w);
            }
        }
        __syncwarp();
        #pragma unroll
        for (int m = 0; m < 2; m++) {
            #pragma unroll
            for (int nt = 0; nt < 4; nt++) {
                int chunk = nch * 4 + nt;
                int row = R0 + m * 16 + gid;
                int off0 = swz(row, chunk) + tig * 4;
                int off8 = swz(row + 8, chunk) + tig * 4;
                uint32_t p01 = tanh2(acc[m][nt][0], acc[m][nt][1]);
                uint32_t p23 = tanh2(acc[m][nt][2], acc[m][nt][3]);
                if (MODE == 1) {
                    p01 = hadd2u(p01, *(uint32_t*)(sm8 + resOff + off0));
                    p23 = hadd2u(p23, *(uint32_t*)(sm8 + resOff + off8));
                }
                if (MODE == 2 && nch == 0) {
                    parked[(m * 4 + nt) * 2]     = p01;
                    parked[(m * 4 + nt) * 2 + 1] = p23;
                } else {
                    *(uint32_t*)(sm8 + dstOff + off0) = p01;
                    *(uint32_t*)(sm8 + dstOff + off8) = p23;
                }
            }
        }
    }
    if (MODE == 2) {
        __syncwarp();
        #pragma unroll
        for (int m = 0; m < 2; m++)
            #pragma unroll
            for (int nt = 0; nt < 4; nt++) {
                int row = R0 + m * 16 + gid;
                *(uint32_t*)(sm8 + dstOff + swz(row, nt) + tig * 4)     = parked[(m * 4 + nt) * 2];
                *(uint32_t*)(sm8 + dstOff + swz(row + 8, nt) + tig * 4) = parked[(m * 4 + nt) * 2 + 1];
            }
    }
}

// L5: 64 -> 128. src = P1 (blk2). cols 0-63 -> P0, 64-127 -> P1 (chunk2 parked).
__device__ __forceinline__ void layer5G(char* sm8, const float* bias, int lane, int R0)
{
    const int gid = lane >> 2, tig = lane & 3;
    const int arow = R0 + (lane & 15);
    const int h = lane >> 4;
    const int ax7 = lane & 7;
    uint32_t aRowBase = cvta_sh(sm8 + OFF_P1) + arow * 128;
    uint32_t parked[16];
    __syncwarp();
    uint32_t a[4][2][4];
    #pragma unroll
    for (int ks = 0; ks < 4; ks++)
        #pragma unroll
        for (int m = 0; m < 2; m++)
            ldsm4(a[ks][m], aRowBase + m * 2048 + ((((2 * ks) | h) ^ ax7) << 4));
    #pragma unroll 2
    for (int nch = 0; nch < 4; nch++) {
        float acc[2][4][4];
        #pragma unroll
        for (int nt = 0; nt < 4; nt++) {
            float2 bc = *reinterpret_cast<const float2*>(bias + nch * 32 + nt * 8 + tig * 2);
            #pragma unroll
            for (int m = 0; m < 2; m++) {
                acc[m][nt][0] = bc.x; acc[m][nt][1] = bc.y;
                acc[m][nt][2] = bc.x; acc[m][nt][3] = bc.y;
            }
        }
        #pragma unroll
        for (int ks = 0; ks < 4; ks++) {
            uint4 bw0 = __ldg(g_w5frag + ((nch * 2 + 0) * 4 + ks) * 32 + lane);
            uint4 bw1 = __ldg(g_w5frag + ((nch * 2 + 1) * 4 + ks) * 32 + lane);
            #pragma unroll
            for (int m = 0; m < 2; m++) {
                mma16816(acc[m][0], a[ks][m], bw0.x, bw0.y);
                mma16816(acc[m][1], a[ks][m], bw0.z, bw0.w);
                mma16816(acc[m][2], a[ks][m], bw1.x, bw1.y);
                mma16816(acc[m][3], a[ks][m], bw1.z, bw1.w);
            }
        }
        int dstOff = (nch < 2) ? OFF_P0 : OFF_P1;
        int dchunk = (nch & 1) * 4;
        __syncwarp();
        #pragma unroll
        for (int m = 0; m < 2; m++) {
            #pragma unroll
            for (int nt = 0; nt < 4; nt++) {
                int chunk = dchunk + nt;
                int row = R0 + m * 16 + gid;
                uint32_t p01 = tanh2(acc[m][nt][0], acc[m][nt][1]);
                uint32_t p23 = tanh2(acc[m][nt][2], acc[m][nt][3]);
                if (nch == 2) {
                    parked[(m * 4 + nt) * 2]     = p01;
                    parked[(m * 4 + nt) * 2 + 1] = p23;
                } else {
                    *(uint32_t*)(sm8 + dstOff + swz(row, chunk) + tig * 4)     = p01;
                    *(uint32_t*)(sm8 + dstOff + swz(row + 8, chunk) + tig * 4) = p23;
                }
            }
        }
    }
    __syncwarp();
    #pragma unroll
    for (int m = 0; m < 2; m++)
        #pragma unroll
        for (int nt = 0; nt < 4; nt++) {
            int row = R0 + m * 16 + gid;
            *(uint32_t*)(sm8 + OFF_P1 + swz(row, nt) + tig * 4)     = parked[(m * 4 + nt) * 2];
            *(uint32_t*)(sm8 + OFF_P1 + swz(row + 8, nt) + tig * 4) = parked[(m * 4 + nt) * 2 + 1];
        }
}

// L6: 128 -> 256, epilogue f32 hw-tanh * smooth + reduce -> AEV
__device__ __forceinline__ void layer6G(char* sm8, const float* bias, int lane, int R0, int wid)
{
    const int gid = lane >> 2, tig = lane & 3;
    const int arow = R0 + (lane & 15);
    const int h = lane >> 4;
    const int ax7 = lane & 7;
    uint32_t aRowBase0 = cvta_sh(sm8 + OFF_P0) + arow * 128;
    uint32_t aRowBase1 = cvta_sh(sm8 + OFF_P1) + arow * 128;
    const float* smoothF = (const float*)(sm8 + OFF_SMOOTH);
    float* aev = (float*)(sm8 + OFF_AEV) + wid * 256;
    float s[2][2];
    __syncwarp();
    #pragma unroll
    for (int m = 0; m < 2; m++) {
        s[m][0] = smoothF[R0 + m * 16 + gid];
        s[m][1] = smoothF[R0 + m * 16 + gid + 8];
    }
    #pragma unroll 2
    for (int nch = 0; nch < 8; nch++) {
        float acc[2][4][4];
        #pragma unroll
        for (int nt = 0; nt < 4; nt++) {
            float2 bc = *reinterpret_cast<const float2*>(bias + nch * 32 + nt * 8 + tig * 2);
            #pragma unroll
            for (int m = 0; m < 2; m++) {
                acc[m][nt][0] = bc.x; acc[m][nt][1] = bc.y;
                acc[m][nt][2] = bc.x; acc[m][nt][3] = bc.y;
            }
        }
        #pragma unroll
        for (int ks = 0; ks < 8; ks++) {
            int ksl = ks & 3;
            uint32_t ab = ((ks < 4) ? aRowBase0 : aRowBase1)
                        + ((((2 * ksl) | h) ^ ax7) << 4);
            uint32_t a[2][4];
            #pragma unroll
            for (int m = 0; m < 2; m++) ldsm4(a[m], ab + m * 2048);
            uint4 bw0 = __ldg(g_w6frag + ((nch * 2 + 0) * 8 + ks) * 32 + lane);
            uint4 bw1 = __ldg(g_w6frag + ((nch * 2 + 1) * 8 + ks) * 32 + lane);
            #pragma unroll
            for (int m = 0; m < 2; m++) {
                mma16816(acc[m][0], a[m], bw0.x, bw0.y);
                mma16816(acc[m][1], a[m], bw0.z, bw0.w);
                mma16816(acc[m][2], a[m], bw1.x, bw1.y);
                mma16816(acc[m][3], a[m], bw1.z, bw1.w);
            }
        }
        float t0[4] = {0.f, 0.f, 0.f, 0.f}, t1[4] = {0.f, 0.f, 0.f, 0.f};
        #pragma unroll
        for (int m = 0; m < 2; m++)
            #pragma unroll
            for (int nt = 0; nt < 4; nt++) {
                t0[nt] += tanh_hw(acc[m][nt][0]) * s[m][0] + tanh_hw(acc[m][nt][2]) * s[m][1];
                t1[nt] += tanh_hw(acc[m][nt][1]) * s[m][0] + tanh_hw(acc[m][nt][3]) * s[m][1];
            }
        #pragma unroll
        for (int nt = 0; nt < 4; nt++) {
            #pragma unroll
            for (int sh = 4; sh < 32; sh <<= 1) {
                t0[nt] += __shfl_xor_sync(0xffffffffu, t0[nt], sh);
                t1[nt] += __shfl_xor_sync(0xffffffffu, t1[nt], sh);
            }
        }
        if (lane < 4) {
            #pragma unroll
            for (int nt = 0; nt < 4; nt++) {
                int col = nch * 32 + nt * 8 + lane * 2;
                aev[col] = t0[nt];
                aev[col + 1] = t1[nt];
            }
        }
    }
}

__global__ void __launch_bounds__(TPB, 2)
Obiwan_84335977825044_kernel(
    const float* __restrict__ gD, const float* __restrict__ gZ,
    const float* __restrict__ W0, const float* __restrict__ b0,
    const float* __restrict__ b1, const float* __restrict__ b2,
    const float* __restrict__ b3, const float* __restrict__ b4,
    const float* __restrict__ b5, const float* __restrict__ b6)
{
    extern __shared__ char sm8[];
    const int tid  = threadIdx.x;
    const int lane = tid & 31;
    const int wid  = tid >> 5;
    const int bidx = blockIdx.x;
    const int center = bidx >> 1;
    const int half = bidx & 1;
    const int b    = center >> 5;
    const int ictr = center & 31;

    float* W0F   = (float*)(sm8 + OFF_W0);
    float* biasF = (float*)(sm8 + OFF_BIAS);
    float* smF   = (float*)(sm8 + OFF_SMOOTH);
    float* sDF   = (float*)(sm8 + OFF_D);
    float* sZF   = (float*)(sm8 + OFF_Z);

    for (int i = tid; i < 1024; i += TPB) sDF[i] = gD[b * 1024 + i];
    if (tid < 32) sZF[tid] = gZ[b * 32 + tid];
    for (int i = tid; i < 576; i += TPB) W0F[i] = W0[i];
    if (tid < 64) {
        biasF[tid] = b0[tid]; biasF[64 + tid] = b1[tid]; biasF[128 + tid] = b2[tid];
        biasF[192 + tid] = b3[tid]; biasF[256 + tid] = b4[tid];
    }
    if (tid < 128) biasF[320 + tid] = b5[tid];
    for (int i = tid; i < 256; i += TPB) biasF[448 + i] = b6[i];
    __syncthreads();

    // ---- L0 (scalar fp32): one row per thread ----
    {
        int r = half * 256 + tid;
        bool valid = (r < 465);
        int rem = valid ? r : 0;
        int a = 0;
        while (rem >= 30 - a) { rem -= 30 - a; a++; }
        int bb2 = a + 1 + rem;
        int j = a + (a >= ictr);
        int k = bb2 + (bb2 >= ictr);

        float Rij = sDF[ictr * 32 + j];
        float Rik = sDF[ictr * 32 + k];
        float Rjk = sDF[j * 32 + k];
        float zi = sZF[ictr], zj = sZF[j], zk = sZF[k];

        float rij2 = Rij * Rij, rik2 = Rik * Rik, rjk2 = Rjk * Rjk;
        float ci = (rij2 + rik2 - rjk2) / fmaxf(2.f * Rij * Rik, 1e-10f);
        float cj = (rij2 + rjk2 - rik2) / fmaxf(2.f * Rij * Rjk, 1e-10f);
        float ck = (rik2 + rjk2 - rij2) / fmaxf(2.f * Rik * Rjk, 1e-10f);

        float g0 = Rij + Rik + Rjk;
        float g1 = Rij * Rik + Rij * Rjk + Rik * Rjk;
        float g2 = Rij * Rik * Rjk;

        float h0 = zi + zj + zk;
        float h1 = ci + cj + ck;
        float h2 = zi * (zj + zk) + zj * zk - ci * (cj + ck) - cj * ck;
        float h3 = zi * (cj + ck) + ci * (zj + zk) + zj * ck + cj * zk;
        float h4 = zi * (zj * zk - cj * ck) - ci * (zj * ck + cj * zk);
        float h5 = zi * (zj * ck + cj * zk) + ci * (zj * zk - cj * ck);

        float ign = 1.f / (sqrtf(g0 * g0 + g1 * g1 + g2 * g2) + 1e-7f);
        float icn = 1.f / (sqrtf(h0 * h0 + h1 * h1 + h2 * h2 + h3 * h3 + h4 * h4 + h5 * h5) + 1e-7f);

        float smooth = 0.f;
        if (valid && Rij < 3.5f && Rik < 3.5f) smooth = fC_cut(Rij) * fC_cut(Rik);
        smF[tid] = smooth;

        float in9[9];
        in9[0] = g0 * ign; in9[1] = g1 * ign; in9[2] = g2 * ign;
        in9[3] = h0 * icn; in9[4] = h1 * icn; in9[5] = h2 * icn;
        in9[6] = h3 * icn; in9[7] = h4 * icn; in9[8] = h5 * icn;
        if (!valid) {
            #pragma unroll
            for (int q = 0; q < 9; q++) in9[q] = 0.f;
        }

        float acc[64];
        #pragma unroll
        for (int o = 0; o < 64; o += 4) {
            float4 bbv = *reinterpret_cast<const float4*>(biasF + o);
            acc[o] = bbv.x; acc[o + 1] = bbv.y; acc[o + 2] = bbv.z; acc[o + 3] = bbv.w;
        }
        #pragma unroll 1
        for (int kk = 0; kk < 9; kk++) {
            float xk = in9[kk];
            const float4* w4 = reinterpret_cast<const float4*>(W0F + kk * 64);
            #pragma unroll
            for (int o = 0; o < 64; o += 4) {
                float4 w = w4[o >> 2];
                acc[o]     = fmaf(xk, w.x, acc[o]);
                acc[o + 1] = fmaf(xk, w.y, acc[o + 1]);
                acc[o + 2] = fmaf(xk, w.z, acc[o + 2]);
                acc[o + 3] = fmaf(xk, w.w, acc[o + 3]);
            }
        }
        #pragma unroll
        for (int o = 0; o < 64; o += 2) {
            *(uint32_t*)(sm8 + OFF_P0 + swz(tid, o >> 3) + (o & 7) * 2) = tanh2(acc[o], acc[o + 1]);
        }
    }
    __syncthreads();

    // ---- warp-tiled MLP: each warp owns rows [32*wid, 32*wid+32) ----
    const int R0 = wid * 32;
    const bool deadWarp = (half * 256 + R0) >= 465;   // whole warp invalid (smooth=0)
    if (deadWarp) {
        float* aev = (float*)(sm8 + OFF_AEV) + wid * 256;
        #pragma unroll
        for (int i = lane; i < 256; i += 32) aev[i] = 0.f;
    } else {
        layerG<1>(sm8, OFF_P0, OFF_P1, OFF_P0, g_w14frag,        biasF + 64,  lane, R0);
        layerG<0>(sm8, OFF_P1, OFF_P0, 0,      g_w14frag + 512,  biasF + 128, lane, R0);
        layerG<2>(sm8, OFF_P0, OFF_P0, 0,      g_w14frag + 1024, biasF + 192, lane, R0);
        layerG<1>(sm8, OFF_P0, OFF_P1, OFF_P1, g_w14frag + 1536, biasF + 256, lane, R0);
        layer5G(sm8, biasF + 320, lane, R0);
        layer6G(sm8, biasF + 448, lane, R0, wid);
    }

    __syncthreads();
    float* aevF = (float*)(sm8 + OFF_AEV);
    float sum = 0.f;
    #pragma unroll
    for (int w = 0; w < 8; ++w) sum += aevF[w * 256 + tid];
    g_part[bidx * 256 + tid] = sum;
}

extern "C" void kernel_launch(void* const* d_in, const int* in_sizes, int n_in,
                              void* d_out, int out_size) {
    const float* D  = (const float*)d_in[0];
    const float* Z  = (const float*)d_in[1];
    const float* W0 = (const float*)d_in[2];  const float* b0 = (const float*)d_in[3];
    const float* W1 = (const float*)d_in[4];  const float* b1 = (const float*)d_in[5];
    const float* W2 = (const float*)d_in[6];  const float* b2 = (const float*)d_in[7];
    const float* W3 = (const float*)d_in[8];  const float* b3 = (const float*)d_in[9];
    const float* W4 = (const float*)d_in[10]; const float* b4 = (const float*)d_in[11];
    const float* W5 = (const float*)d_in[12]; const float* b5 = (const float*)d_in[13];
    const float* W6 = (const float*)d_in[14]; const float* b6 = (const float*)d_in[15];

    pack_weights<<<28, 256>>>(W1, W2, W3, W4, W5, W6);

    cudaFuncSetAttribute(Obiwan_84335977825044_kernel,
                         cudaFuncAttributeMaxDynamicSharedMemorySize, SMEM_BYTES);
    Obiwan_84335977825044_kernel<<<2048, TPB, SMEM_BYTES>>>(
        D, Z, W0, b0, b1, b2, b3, b4, b5, b6);

    reduce_out<<<512, 512>>>((float*)d_out);
}

// round 13
// speedup vs baseline: 1.1350x; 1.1350x over previous
#include <cuda_runtime.h>
#include <cuda_fp16.h>
#include <stdint.h>

#define TPB 256

// ---- dynamic smem layout (byte offsets) ----
#define OFF_P0     0         // plane0 fp16 [256][72]
#define OFF_P1     36864     // plane1 fp16 [256][72]
#define OFF_D      73728     // 1024 fp32
#define OFF_Z      77824     // 32 fp32
#define OFF_SMOOTH 77952     // 256 fp32
#define OFF_BIAS   78976     // 704 fp32: b0|b1|b2|b3|b4|b5|b6
#define OFF_AEV    81792     // 8 warps * 256 fp32
#define SMEM_BYTES 90112

// weight fragments packed as PAIRS of adjacent n-tiles -> one uint4 (LDG.128)
__device__ uint4 g_w0frag[128];     // W0: k padded 9->16, 4 pair-groups
__device__ uint4 g_w14frag[2048];   // W1..W4: 512 uint4 per layer
__device__ uint4 g_w5frag[1024];    // W5
__device__ uint4 g_w6frag[4096];    // W6
__device__ float g_part[2048 * 256];

__device__ __forceinline__ uint32_t cvta_sh(const void* p) {
    return (uint32_t)__cvta_generic_to_shared(p);
}
__device__ __forceinline__ void ldsm4(uint32_t* r, uint32_t addr) {
    asm volatile("ldmatrix.sync.aligned.m8n8.x4.shared.b16 {%0,%1,%2,%3}, [%4];"
        : "=r"(r[0]), "=r"(r[1]), "=r"(r[2]), "=r"(r[3]) : "r"(addr));
}
__device__ __forceinline__ void mma16816(float* d, const uint32_t* a, uint32_t b0, uint32_t b1) {
    asm volatile("mma.sync.aligned.m16n8k16.row.col.f32.f16.f16.f32 "
        "{%0,%1,%2,%3}, {%4,%5,%6,%7}, {%8,%9}, {%0,%1,%2,%3};"
        : "+f"(d[0]), "+f"(d[1]), "+f"(d[2]), "+f"(d[3])
        : "r"(a[0]), "r"(a[1]), "r"(a[2]), "r"(a[3]), "r"(b0), "r"(b1));
}
__device__ __forceinline__ uint32_t tanh2(float a, float b) {
    __half2 h = __floats2half2_rn(a, b);
    uint32_t u = *reinterpret_cast<uint32_t*>(&h);
    uint32_t y;
    asm("tanh.approx.f16x2 %0, %1;" : "=r"(y) : "r"(u));
    return y;
}
__device__ __forceinline__ uint32_t hadd2u(uint32_t a, uint32_t b) {
    uint32_t y;
    asm("add.f16x2 %0, %1, %2;" : "=r"(y) : "r"(a), "r"(b));
    return y;
}
__device__ __forceinline__ float tanh_hw(float x) {
    float y;
    asm("tanh.approx.f32 %0, %1;" : "=f"(y) : "f"(x));
    return y;
}
__device__ __forceinline__ float fC_cut(float d) {
    return 0.5f * cosf(0.89759790102565521f * d) + 0.5f;
}

// pack weights into PAIRED B fragments. 7296 threads.
__global__ void pack_weights(const float* __restrict__ W0,
                             const float* __restrict__ W1, const float* __restrict__ W2,
                             const float* __restrict__ W3, const float* __restrict__ W4,
                             const float* __restrict__ W5, const float* __restrict__ W6) {
    int t = blockIdx.x * 256 + threadIdx.x;
    if (t >= 7296) return;
    int gi = t >> 5, l = t & 31;
    const float* W; uint4* dst; int nch, p, ks, N, idx;
    int kmax = 1 << 30;
    if (gi < 64) {
        int L = gi >> 4, rel = gi & 15;
        W = (L == 0) ? W1 : (L == 1) ? W2 : (L == 2) ? W3 : W4;
        nch = rel >> 3; p = (rel >> 2) & 1; ks = rel & 3;
        dst = g_w14frag + L * 512; N = 64;
        idx = ((nch * 2 + p) * 4 + ks) * 32 + l;
    } else if (gi < 96) {
        int rel = gi - 64;
        W = W5; nch = rel >> 3; p = (rel >> 2) & 1; ks = rel & 3;
        dst = g_w5frag; N = 128;
        idx = ((nch * 2 + p) * 4 + ks) * 32 + l;
    } else if (gi < 224) {
        int rel = gi - 96;
        W = W6; nch = rel >> 4; p = (rel >> 3) & 1; ks = rel & 7;
        dst = g_w6frag; N = 256;
        idx = ((nch * 2 + p) * 8 + ks) * 32 + l;
    } else {
        int rel = gi - 224;           // 0..3
        W = W0; nch = rel >> 1; p = rel & 1; ks = 0;
        dst = g_w0frag; N = 64; kmax = 9;   // zero-pad k 9..15
        idx = (nch * 2 + p) * 32 + l;
    }
    int k = ks * 16 + (l & 3) * 2;
    int r = l >> 2;
    uint4 u;
    {
        int n = (nch * 4 + 2 * p) * 8 + r;
        float w0v = (k     < kmax) ? W[k * N + n]       : 0.f;
        float w1v = (k + 1 < kmax) ? W[(k + 1) * N + n] : 0.f;
        float w2v = (k + 8 < kmax) ? W[(k + 8) * N + n] : 0.f;
        float w3v = (k + 9 < kmax) ? W[(k + 9) * N + n] : 0.f;
        __half2 h0 = __floats2half2_rn(w0v, w1v);
        __half2 h1 = __floats2half2_rn(w2v, w3v);
        u.x = *reinterpret_cast<uint32_t*>(&h0);
        u.y = *reinterpret_cast<uint32_t*>(&h1);
    }
    {
        int n = (nch * 4 + 2 * p + 1) * 8 + r;
        float w0v = (k     < kmax) ? W[k * N + n]       : 0.f;
        float w1v = (k + 1 < kmax) ? W[(k + 1) * N + n] : 0.f;
        float w2v = (k + 8 < kmax) ? W[(k + 8) * N + n] : 0.f;
        float w3v = (k + 9 < kmax) ? W[(k + 9) * N + n] : 0.f;
        __half2 h0 = __floats2half2_rn(w0v, w1v);
        __half2 h1 = __floats2half2_rn(w2v, w3v);
        u.z = *reinterpret_cast<uint32_t*>(&h0);
        u.w = *reinterpret_cast<uint32_t*>(&h1);
    }
    dst[idx] = u;
}

__global__ void reduce_out(float* __restrict__ out) {
    int i = blockIdx.x * 512 + threadIdx.x;
    int center = i >> 8, c = i & 255;
    out[i] = g_part[center * 512 + c] + g_part[center * 512 + 256 + c];
}

// 64->64 mma layer, warp owns 32 rows. nch fully unrolled for cross-chunk ILP.
template<int MODE>
__device__ __forceinline__ void layerG(char* sm8, int srcOff, int dstOff, int resOff,
                                       const uint4* __restrict__ frag,
                                       const float* bias, int lane, int R0)
{
    const int gid = lane >> 2, tig = lane & 3;
    uint32_t aBase = cvta_sh(sm8 + srcOff) + (R0 + (lane & 15)) * 144 + (lane >> 4) * 16;
    uint32_t parked[16];
    __syncwarp();
    uint32_t a[4][2][4];
    #pragma unroll
    for (int ks = 0; ks < 4; ks++)
        #pragma unroll
        for (int m = 0; m < 2; m++) ldsm4(a[ks][m], aBase + m * 2304 + ks * 32);
    #pragma unroll
    for (int nch = 0; nch < 2; nch++) {
        float acc[2][4][4];
        #pragma unroll
        for (int nt = 0; nt < 4; nt++) {
            float2 bc = *reinterpret_cast<const float2*>(bias + nch * 32 + nt * 8 + tig * 2);
            #pragma unroll
            for (int m = 0; m < 2; m++) {
                acc[m][nt][0] = bc.x; acc[m][nt][1] = bc.y;
                acc[m][nt][2] = bc.x; acc[m][nt][3] = bc.y;
            }
        }
        #pragma unroll
        for (int ks = 0; ks < 4; ks++) {
            uint4 bw0 = __ldg(frag + ((nch * 2 + 0) * 4 + ks) * 32 + lane);
            uint4 bw1 = __ldg(frag + ((nch * 2 + 1) * 4 + ks) * 32 + lane);
            #pragma unroll
            for (int m = 0; m < 2; m++) {
                mma16816(acc[m][0], a[ks][m], bw0.x, bw0.y);
                mma16816(acc[m][1], a[ks][m], bw0.z, bw0.w);
                mma16816(acc[m][2], a[ks][m], bw1.x, bw1.y);
                mma16816(acc[m][3], a[ks][m], bw1.z, bw1.w);
            }
        }
        __syncwarp();
        #pragma unroll
        for (int m = 0; m < 2; m++) {
            #pragma unroll
            for (int nt = 0; nt < 4; nt++) {
                int col = nch * 32 + nt * 8 + tig * 2;
                int row = R0 + m * 16 + gid;
                uint32_t p01 = tanh2(acc[m][nt][0], acc[m][nt][1]);
                uint32_t p23 = tanh2(acc[m][nt][2], acc[m][nt][3]);
                if (MODE == 1) {
                    p01 = hadd2u(p01, *(uint32_t*)(sm8 + resOff + row * 144 + col * 2));
                    p23 = hadd2u(p23, *(uint32_t*)(sm8 + resOff + (row + 8) * 144 + col * 2));
                }
                if (MODE == 2 && nch == 0) {
                    parked[(m * 4 + nt) * 2]     = p01;
                    parked[(m * 4 + nt) * 2 + 1] = p23;
                } else {
                    *(uint32_t*)(sm8 + dstOff + row * 144 + col * 2) = p01;
                    *(uint32_t*)(sm8 + dstOff + (row + 8) * 144 + col * 2) = p23;
                }
            }
        }
    }
    if (MODE == 2) {
        __syncwarp();
        #pragma unroll
        for (int m = 0; m < 2; m++)
            #pragma unroll
            for (int nt = 0; nt < 4; nt++) {
                int col = nt * 8 + tig * 2;
                int row = R0 + m * 16 + gid;
                *(uint32_t*)(sm8 + dstOff + row * 144 + col * 2)       = parked[(m * 4 + nt) * 2];
                *(uint32_t*)(sm8 + dstOff + (row + 8) * 144 + col * 2) = parked[(m * 4 + nt) * 2 + 1];
            }
    }
}

// L5: 64 -> 128. A hoisted; cols 0-63 -> P0, 64-127 -> P1 (chunk2 parked).
__device__ __forceinline__ void layer5G(char* sm8, const float* bias, int lane, int R0)
{
    const int gid = lane >> 2, tig = lane & 3;
    uint32_t aBase = cvta_sh(sm8 + OFF_P1) + (R0 + (lane & 15)) * 144 + (lane >> 4) * 16;
    uint32_t parked[16];
    __syncwarp();
    uint32_t a[4][2][4];
    #pragma unroll
    for (int ks = 0; ks < 4; ks++)
        #pragma unroll
        for (int m = 0; m < 2; m++) ldsm4(a[ks][m], aBase + m * 2304 + ks * 32);
    #pragma unroll 2
    for (int nch = 0; nch < 4; nch++) {
        float acc[2][4][4];
        #pragma unroll
        for (int nt = 0; nt < 4; nt++) {
            float2 bc = *reinterpret_cast<const float2*>(bias + nch * 32 + nt * 8 + tig * 2);
            #pragma unroll
            for (int m = 0; m < 2; m++) {
                acc[m][nt][0] = bc.x; acc[m][nt][1] = bc.y;
                acc[m][nt][2] = bc.x; acc[m][nt][3] = bc.y;
            }
        }
        #pragma unroll
        for (int ks = 0; ks < 4; ks++) {
            uint4 bw0 = __ldg(g_w5frag + ((nch * 2 + 0) * 4 + ks) * 32 + lane);
            uint4 bw1 = __ldg(g_w5frag + ((nch * 2 + 1) * 4 + ks) * 32 + lane);
            #pragma unroll
            for (int m = 0; m < 2; m++) {
                mma16816(acc[m][0], a[ks][m], bw0.x, bw0.y);
                mma16816(acc[m][1], a[ks][m], bw0.z, bw0.w);
                mma16816(acc[m][2], a[ks][m], bw1.x, bw1.y);
                mma16816(acc[m][3], a[ks][m], bw1.z, bw1.w);
            }
        }
        int dstOff = (nch < 2) ? OFF_P0 : OFF_P1;
        int dcol = (nch & 1) * 32;
        __syncwarp();
        #pragma unroll
        for (int m = 0; m < 2; m++) {
            #pragma unroll
            for (int nt = 0; nt < 4; nt++) {
                int col = dcol + nt * 8 + tig * 2;
                int row = R0 + m * 16 + gid;
                uint32_t p01 = tanh2(acc[m][nt][0], acc[m][nt][1]);
                uint32_t p23 = tanh2(acc[m][nt][2], acc[m][nt][3]);
                if (nch == 2) {
                    parked[(m * 4 + nt) * 2]     = p01;
                    parked[(m * 4 + nt) * 2 + 1] = p23;
                } else {
                    *(uint32_t*)(sm8 + dstOff + row * 144 + col * 2) = p01;
                    *(uint32_t*)(sm8 + dstOff + (row + 8) * 144 + col * 2) = p23;
                }
            }
        }
    }
    __syncwarp();
    #pragma unroll
    for (int m = 0; m < 2; m++)
        #pragma unroll
        for (int nt = 0; nt < 4; nt++) {
            int col = nt * 8 + tig * 2;
            int row = R0 + m * 16 + gid;
            *(uint32_t*)(sm8 + OFF_P1 + row * 144 + col * 2)       = parked[(m * 4 + nt) * 2];
            *(uint32_t*)(sm8 + OFF_P1 + (row + 8) * 144 + col * 2) = parked[(m * 4 + nt) * 2 + 1];
        }
}

// L6: 128 -> 256, epilogue f32 hw-tanh * smooth + reduce -> AEV
__device__ __forceinline__ void layer6G(char* sm8, const float* bias, int lane, int R0, int wid)
{
    const int gid = lane >> 2, tig = lane & 3;
    uint32_t aBase0 = cvta_sh(sm8 + OFF_P0) + (R0 + (lane & 15)) * 144 + (lane >> 4) * 16;
    uint32_t aBase1 = cvta_sh(sm8 + OFF_P1) + (R0 + (lane & 15)) * 144 + (lane >> 4) * 16;
    const float* smoothF = (const float*)(sm8 + OFF_SMOOTH);
    float* aev = (float*)(sm8 + OFF_AEV) + wid * 256;
    float s[2][2];
    __syncwarp();
    #pragma unroll
    for (int m = 0; m < 2; m++) {
        s[m][0] = smoothF[R0 + m * 16 + gid];
        s[m][1] = smoothF[R0 + m * 16 + gid + 8];
    }
    #pragma unroll 2
    for (int nch = 0; nch < 8; nch++) {
        float acc[2][4][4];
        #pragma unroll
        for (int nt = 0; nt < 4; nt++) {
            float2 bc = *reinterpret_cast<const float2*>(bias + nch * 32 + nt * 8 + tig * 2);
            #pragma unroll
            for (int m = 0; m < 2; m++) {
                acc[m][nt][0] = bc.x; acc[m][nt][1] = bc.y;
                acc[m][nt][2] = bc.x; acc[m][nt][3] = bc.y;
            }
        }
        #pragma unroll
        for (int ks = 0; ks < 8; ks++) {
            uint32_t ab = (ks < 4) ? (aBase0 + ks * 32) : (aBase1 + (ks - 4) * 32);
            uint32_t a[2][4];
            #pragma unroll
            for (int m = 0; m < 2; m++) ldsm4(a[m], ab + m * 2304);
            uint4 bw0 = __ldg(g_w6frag + ((nch * 2 + 0) * 8 + ks) * 32 + lane);
            uint4 bw1 = __ldg(g_w6frag + ((nch * 2 + 1) * 8 + ks) * 32 + lane);
            #pragma unroll
            for (int m = 0; m < 2; m++) {
                mma16816(acc[m][0], a[m], bw0.x, bw0.y);
                mma16816(acc[m][1], a[m], bw0.z, bw0.w);
                mma16816(acc[m][2], a[m], bw1.x, bw1.y);
                mma16816(acc[m][3], a[m], bw1.z, bw1.w);
            }
        }
        float t0[4] = {0.f, 0.f, 0.f, 0.f}, t1[4] = {0.f, 0.f, 0.f, 0.f};
        #pragma unroll
        for (int m = 0; m < 2; m++)
            #pragma unroll
            for (int nt = 0; nt < 4; nt++) {
                t0[nt] += tanh_hw(acc[m][nt][0]) * s[m][0] + tanh_hw(acc[m][nt][2]) * s[m][1];
                t1[nt] += tanh_hw(acc[m][nt][1]) * s[m][0] + tanh_hw(acc[m][nt][3]) * s[m][1];
            }
        #pragma unroll
        for (int nt = 0; nt < 4; nt++) {
            #pragma unroll
            for (int sh = 4; sh < 32; sh <<= 1) {
                t0[nt] += __shfl_xor_sync(0xffffffffu, t0[nt], sh);
                t1[nt] += __shfl_xor_sync(0xffffffffu, t1[nt], sh);
            }
        }
        if (lane < 4) {
            #pragma unroll
            for (int nt = 0; nt < 4; nt++) {
                int col = nch * 32 + nt * 8 + lane * 2;
                aev[col] = t0[nt];
                aev[col + 1] = t1[nt];
            }
        }
    }
}

__global__ void __launch_bounds__(TPB, 2)
Obiwan_84335977825044_kernel(
    const float* __restrict__ gD, const float* __restrict__ gZ,
    const float* __restrict__ b0, const float* __restrict__ b1,
    const float* __restrict__ b2, const float* __restrict__ b3,
    const float* __restrict__ b4, const float* __restrict__ b5,
    const float* __restrict__ b6)
{
    extern __shared__ char sm8[];
    const int tid  = threadIdx.x;
    const int lane = tid & 31;
    const int wid  = tid >> 5;
    const int bidx = blockIdx.x;
    const int center = bidx >> 1;
    const int half = bidx & 1;
    const int b    = center >> 5;
    const int ictr = center & 31;

    float* biasF = (float*)(sm8 + OFF_BIAS);
    float* smF   = (float*)(sm8 + OFF_SMOOTH);
    float* sDF   = (float*)(sm8 + OFF_D);
    float* sZF   = (float*)(sm8 + OFF_Z);

    for (int i = tid; i < 1024; i += TPB) sDF[i] = gD[b * 1024 + i];
    if (tid < 32) sZF[tid] = gZ[b * 32 + tid];
    if (tid < 64) {
        biasF[tid] = b0[tid]; biasF[64 + tid] = b1[tid]; biasF[128 + tid] = b2[tid];
        biasF[192 + tid] = b3[tid]; biasF[256 + tid] = b4[tid];
    }
    if (tid < 128) biasF[320 + tid] = b5[tid];
    for (int i = tid; i < 256; i += TPB) biasF[448 + i] = b6[i];
    __syncthreads();

    // ---- features: one row per thread; stage in9 (fp16, padded to 16) into P1 ----
    {
        int r = half * 256 + tid;
        bool valid = (r < 465);
        int rem = valid ? r : 0;
        int a = 0;
        while (rem >= 30 - a) { rem -= 30 - a; a++; }
        int bb2 = a + 1 + rem;
        int j = a + (a >= ictr);
        int k = bb2 + (bb2 >= ictr);

        float Rij = sDF[ictr * 32 + j];
        float Rik = sDF[ictr * 32 + k];
        float Rjk = sDF[j * 32 + k];
        float zi = sZF[ictr], zj = sZF[j], zk = sZF[k];

        float rij2 = Rij * Rij, rik2 = Rik * Rik, rjk2 = Rjk * Rjk;
        float ci = (rij2 + rik2 - rjk2) / fmaxf(2.f * Rij * Rik, 1e-10f);
        float cj = (rij2 + rjk2 - rik2) / fmaxf(2.f * Rij * Rjk, 1e-10f);
        float ck = (rik2 + rjk2 - rij2) / fmaxf(2.f * Rik * Rjk, 1e-10f);

        float g0 = Rij + Rik + Rjk;
        float g1 = Rij * Rik + Rij * Rjk + Rik * Rjk;
        float g2 = Rij * Rik * Rjk;

        float h0 = zi + zj + zk;
        float h1 = ci + cj + ck;
        float h2 = zi * (zj + zk) + zj * zk - ci * (cj + ck) - cj * ck;
        float h3 = zi * (cj + ck) + ci * (zj + zk) + zj * ck + cj * zk;
        float h4 = zi * (zj * zk - cj * ck) - ci * (zj * ck + cj * zk);
        float h5 = zi * (zj * ck + cj * zk) + ci * (zj * zk - cj * ck);

        float ign = 1.f / (sqrtf(g0 * g0 + g1 * g1 + g2 * g2) + 1e-7f);
        float icn = 1.f / (sqrtf(h0 * h0 + h1 * h1 + h2 * h2 + h3 * h3 + h4 * h4 + h5 * h5) + 1e-7f);

        float smooth = 0.f;
        if (valid && Rij < 3.5f && Rik < 3.5f) smooth = fC_cut(Rij) * fC_cut(Rik);
        smF[tid] = smooth;

        float in9[9];
        in9[0] = g0 * ign; in9[1] = g1 * ign; in9[2] = g2 * ign;
        in9[3] = h0 * icn; in9[4] = h1 * icn; in9[5] = h2 * icn;
        in9[6] = h3 * icn; in9[7] = h4 * icn; in9[8] = h5 * icn;
        if (!valid) {
            #pragma unroll
            for (int q = 0; q < 9; q++) in9[q] = 0.f;
        }

        uint32_t base = OFF_P1 + tid * 144;
        uint32_t* dst = (uint32_t*)(sm8 + base);
        __half2 h01 = __floats2half2_rn(in9[0], in9[1]);
        __half2 h23 = __floats2half2_rn(in9[2], in9[3]);
        __half2 h45 = __floats2half2_rn(in9[4], in9[5]);
        __half2 h67 = __floats2half2_rn(in9[6], in9[7]);
        __half2 h8x = __floats2half2_rn(in9[8], 0.f);
        dst[0] = *reinterpret_cast<uint32_t*>(&h01);
        dst[1] = *reinterpret_cast<uint32_t*>(&h23);
        dst[2] = *reinterpret_cast<uint32_t*>(&h45);
        dst[3] = *reinterpret_cast<uint32_t*>(&h67);
        dst[4] = *reinterpret_cast<uint32_t*>(&h8x);
        dst[5] = 0; dst[6] = 0; dst[7] = 0;
    }
    __syncthreads();

    // ---- warp-tiled MLP: each warp owns rows [32*wid, 32*wid+32) ----
    const int R0 = wid * 32;
    const int gid = lane >> 2, tig = lane & 3;
    const bool deadWarp = (half * 256 + R0) >= 465;   // whole warp invalid (smooth=0)
    if (deadWarp) {
        float* aev = (float*)(sm8 + OFF_AEV) + wid * 256;
        #pragma unroll
        for (int i = lane; i < 256; i += 32) aev[i] = 0.f;
    } else {
        // ---- L0 as mma: A = in9 staged in P1 (k=16), B = g_w0frag; out -> P0 ----
        {
            uint32_t aBase = cvta_sh(sm8 + OFF_P1) + (R0 + (lane & 15)) * 144 + (lane >> 4) * 16;
            uint32_t a[2][4];
            ldsm4(a[0], aBase);
            ldsm4(a[1], aBase + 16 * 144);
            #pragma unroll
            for (int nch = 0; nch < 2; nch++) {
                float acc[2][4][4];
                #pragma unroll
                for (int nt = 0; nt < 4; nt++) {
                    float2 bc = *reinterpret_cast<const float2*>(biasF + nch * 32 + nt * 8 + tig * 2);
                    #pragma unroll
                    for (int m = 0; m < 2; m++) {
                        acc[m][nt][0] = bc.x; acc[m][nt][1] = bc.y;
                        acc[m][nt][2] = bc.x; acc[m][nt][3] = bc.y;
                    }
                }
                uint4 bw0 = __ldg(g_w0frag + (nch * 2 + 0) * 32 + lane);
                uint4 bw1 = __ldg(g_w0frag + (nch * 2 + 1) * 32 + lane);
                #pragma unroll
                for (int m = 0; m < 2; m++) {
                    mma16816(acc[m][0], a[m], bw0.x, bw0.y);
                    mma16816(acc[m][1], a[m], bw0.z, bw0.w);
                    mma16816(acc[m][2], a[m], bw1.x, bw1.y);
                    mma16816(acc[m][3], a[m], bw1.z, bw1.w);
                }
                #pragma unroll
                for (int m = 0; m < 2; m++) {
                    #pragma unroll
                    for (int nt = 0; nt < 4; nt++) {
                        int col = nch * 32 + nt * 8 + tig * 2;
                        int row = R0 + m * 16 + gid;
                        *(uint32_t*)(sm8 + OFF_P0 + row * 144 + col * 2) =
                            tanh2(acc[m][nt][0], acc[m][nt][1]);
                        *(uint32_t*)(sm8 + OFF_P0 + (row + 8) * 144 + col * 2) =
                            tanh2(acc[m][nt][2], acc[m][nt][3]);
                    }
                }
            }
        }
        layerG<1>(sm8, OFF_P0, OFF_P1, OFF_P0, g_w14frag,        biasF + 64,  lane, R0);
        layerG<0>(sm8, OFF_P1, OFF_P0, 0,      g_w14frag + 512,  biasF + 128, lane, R0);
        layerG<2>(sm8, OFF_P0, OFF_P0, 0,      g_w14frag + 1024, biasF + 192, lane, R0);
        layerG<1>(sm8, OFF_P0, OFF_P1, OFF_P1, g_w14frag + 1536, biasF + 256, lane, R0);
        layer5G(sm8, biasF + 320, lane, R0);
        layer6G(sm8, biasF + 448, lane, R0, wid);
    }

    __syncthreads();
    float* aevF = (float*)(sm8 + OFF_AEV);
    float sum = 0.f;
    #pragma unroll
    for (int w = 0; w < 8; ++w) sum += aevF[w * 256 + tid];
    g_part[bidx * 256 + tid] = sum;
}

extern "C" void kernel_launch(void* const* d_in, const int* in_sizes, int n_in,
                              void* d_out, int out_size) {
    const float* D  = (const float*)d_in[0];
    const float* Z  = (const float*)d_in[1];
    const float* W0 = (const float*)d_in[2];  const float* b0 = (const float*)d_in[3];
    const float* W1 = (const float*)d_in[4];  const float* b1 = (const float*)d_in[5];
    const float* W2 = (const float*)d_in[6];  const float* b2 = (const float*)d_in[7];
    const float* W3 = (const float*)d_in[8];  const float* b3 = (const float*)d_in[9];
    const float* W4 = (const float*)d_in[10]; const float* b4 = (const float*)d_in[11];
    const float* W5 = (const float*)d_in[12]; const float* b5 = (const float*)d_in[13];
    const float* W6 = (const float*)d_in[14]; const float* b6 = (const float*)d_in[15];

    pack_weights<<<29, 256>>>(W0, W1, W2, W3, W4, W5, W6);

    cudaFuncSetAttribute(Obiwan_84335977825044_kernel,
                         cudaFuncAttributeMaxDynamicSharedMemorySize, SMEM_BYTES);
    Obiwan_84335977825044_kernel<<<2048, TPB, SMEM_BYTES>>>(
        D, Z, b0, b1, b2, b3, b4, b5, b6);

    reduce_out<<<512, 512>>>((float*)d_out);
}